// round 4
// baseline (speedup 1.0000x reference)
#include <cuda_runtime.h>
#include <math_constants.h>

// Problem constants (fixed shapes per reference)
#define M_TOTAL   16384          // 8*64*32 samples
#define DIM       128
#define NCODES    10000
#define NTILE     128
#define NTILES    79             // ceil(10000/128)
#define NPAD      (NTILES * NTILE)
#define MTILE     64
#define KC        16
#define AS_STRIDE 68             // padded k-major A tile stride (keeps float4 alignment)

__device__ float g_cnorm[NPAD];
__device__ float g_loss;

// ---- packed fp32x2 helpers (Blackwell-only; ptxas never emits these itself) ----
__device__ __forceinline__ unsigned long long pack2(float x, float y) {
    unsigned long long r;
    asm("mov.b64 %0, {%1, %2};" : "=l"(r) : "f"(x), "f"(y));
    return r;
}
__device__ __forceinline__ float2 unpack2(unsigned long long v) {
    float2 r;
    asm("mov.b64 {%0, %1}, %2;" : "=f"(r.x), "=f"(r.y) : "l"(v));
    return r;
}
__device__ __forceinline__ void ffma2(unsigned long long &acc,
                                      unsigned long long a, unsigned long long b) {
    asm("fma.rn.f32x2 %0, %1, %2, %0;" : "+l"(acc) : "l"(a), "l"(b));
}

// ---- kernel 1: per-code squared norms (+INF padding), zero loss accumulator ----
__global__ void cnorm_kernel(const float* __restrict__ cm) {
    int j = blockIdx.x * blockDim.x + threadIdx.x;
    if (j == 0) g_loss = 0.0f;
    if (j >= NPAD) return;
    float s = CUDART_INF_F;
    if (j < NCODES) {
        s = 0.0f;
        #pragma unroll 8
        for (int k = 0; k < DIM; ++k) {
            float v = cm[(size_t)k * NCODES + j];
            s = fmaf(v, v, s);
        }
    }
    g_cnorm[j] = s;
}

// ---- kernel 2: fused distance-GEMM + argmin + gather + loss partials ----
// Block: 64 samples x all 10000 codes. 256 threads: tx = lane (0..31, 4 codes each),
// ty = warp (0..7, 8 samples each). Accumulators are f32x2 pairs along M.
__global__ void __launch_bounds__(256, 2)
vq_main_kernel(const float* __restrict__ inp, const float* __restrict__ cm,
               float* __restrict__ out) {
    __shared__ __align__(16) float As[DIM * AS_STRIDE];  // k-major sample tile
    __shared__ __align__(16) float Bs[KC][NTILE];
    __shared__ __align__(16) float Cs[NTILE];
    __shared__ int   sbi[MTILE];
    __shared__ float wsum[8];

    const int tid = threadIdx.x;
    const int tx  = tid & 31;   // lane
    const int ty  = tid >> 5;   // warp id
    const int s0  = blockIdx.x * MTILE;

    // Load + transpose A tile: As[k][s]  (one-time; store conflicts acceptable)
    #pragma unroll
    for (int r = 0; r < (MTILE * DIM / 4) / 256; ++r) {   // 8 iters
        int idx4 = r * 256 + tid;
        int s  = idx4 >> 5;
        int k4 = (idx4 & 31) << 2;
        float4 v = *(const float4*)(inp + (size_t)(s0 + s) * DIM + k4);
        As[(k4 + 0) * AS_STRIDE + s] = v.x;
        As[(k4 + 1) * AS_STRIDE + s] = v.y;
        As[(k4 + 2) * AS_STRIDE + s] = v.z;
        As[(k4 + 3) * AS_STRIDE + s] = v.w;
    }

    float bd[8];
    int   bi[8];
    #pragma unroll
    for (int i = 0; i < 8; ++i) { bd[i] = CUDART_INF_F; bi[i] = 0; }

    #pragma unroll 1
    for (int t = 0; t < NTILES; ++t) {
        unsigned long long acc[4][4];
        #pragma unroll
        for (int ip = 0; ip < 4; ++ip)
            #pragma unroll
            for (int j = 0; j < 4; ++j) acc[ip][j] = 0ull;

        #pragma unroll 1
        for (int kc = 0; kc < DIM / KC; ++kc) {
            __syncthreads();   // protect Bs/Cs reuse
            // Stage B chunk: Bs[k][n], 512 float4 / 256 threads
            #pragma unroll
            for (int r = 0; r < 2; ++r) {
                int idx4 = r * 256 + tid;
                int k  = idx4 >> 5;
                int n4 = (idx4 & 31) << 2;
                int col = t * NTILE + n4;
                if (col > NCODES - 4) col = NCODES - 4;   // clamp; padded cols excluded via INF cnorm
                *(float4*)&Bs[k][n4] =
                    *(const float4*)(cm + (size_t)(kc * KC + k) * NCODES + col);
            }
            if (kc == 0 && tid < 32) {
                *(float4*)&Cs[tid * 4] = *(const float4*)(g_cnorm + t * NTILE + tid * 4);
            }
            __syncthreads();

            #pragma unroll
            for (int k = 0; k < KC; ++k) {
                const float* ap = &As[(kc * KC + k) * AS_STRIDE + ty * 8];
                ulonglong2 aA = *(const ulonglong2*)ap;         // samples (0,1),(2,3)
                ulonglong2 aB = *(const ulonglong2*)(ap + 4);   // samples (4,5),(6,7)
                float4 bv = *(const float4*)&Bs[k][tx * 4];
                unsigned long long a2[4] = { aA.x, aA.y, aB.x, aB.y };
                unsigned long long b2[4] = { pack2(bv.x, bv.x), pack2(bv.y, bv.y),
                                             pack2(bv.z, bv.z), pack2(bv.w, bv.w) };
                #pragma unroll
                for (int ip = 0; ip < 4; ++ip)
                    #pragma unroll
                    for (int j = 0; j < 4; ++j)
                        ffma2(acc[ip][j], a2[ip], b2[j]);
            }
        }

        // Tile epilogue: dist = ||c||^2 - 2 x.c ; fold into running argmin
        #pragma unroll
        for (int j = 0; j < 4; ++j) {
            int nl = tx * 4 + j;
            int gn = t * NTILE + nl;
            float cn = Cs[nl];
            #pragma unroll
            for (int ip = 0; ip < 4; ++ip) {
                float2 d2 = unpack2(acc[ip][j]);
                float d0 = fmaf(-2.0f, d2.x, cn);
                float d1 = fmaf(-2.0f, d2.y, cn);
                int i0 = 2 * ip, i1 = 2 * ip + 1;
                if (d0 < bd[i0]) { bd[i0] = d0; bi[i0] = gn; }
                if (d1 < bd[i1]) { bd[i1] = d1; bi[i1] = gn; }
            }
        }
    }

    // Cross-lane argmin: each warp holds all candidates for its 8 samples.
    #pragma unroll
    for (int i = 0; i < 8; ++i) {
        #pragma unroll
        for (int o = 16; o > 0; o >>= 1) {
            float od = __shfl_xor_sync(0xffffffffu, bd[i], o);
            int   oi = __shfl_xor_sync(0xffffffffu, bi[i], o);
            if (od < bd[i] || (od == bd[i] && oi < bi[i])) { bd[i] = od; bi[i] = oi; }
        }
        if (tx == 0) sbi[ty * 8 + i] = bi[i];
    }
    __syncthreads();

    // Gather winning codes, write outputs (x + (q-x), matching reference rounding),
    // accumulate squared-error partial.
    float lsum = 0.0f;
    #pragma unroll
    for (int r = 0; r < MTILE * DIM / 256; ++r) {   // 32 iters
        int idx = r * 256 + tid;
        int s = idx >> 7;
        int k = idx & (DIM - 1);
        int c = sbi[s];
        float q = cm[(size_t)k * NCODES + c];
        float x = As[k * AS_STRIDE + s];
        float d = q - x;
        out[(size_t)(s0 + s) * DIM + k] = x + d;
        lsum = fmaf(d, d, lsum);
    }
    #pragma unroll
    for (int o = 16; o > 0; o >>= 1) lsum += __shfl_xor_sync(0xffffffffu, lsum, o);
    if (tx == 0) wsum[ty] = lsum;
    __syncthreads();
    if (tid == 0) {
        float s = 0.0f;
        #pragma unroll
        for (int i = 0; i < 8; ++i) s += wsum[i];
        atomicAdd(&g_loss, s);
    }
}

// ---- kernel 3: loss = q_loss + 0.25*e_loss = 1.25 * mean((q-x)^2) ----
__global__ void finalize_kernel(float* __restrict__ dst) {
    *dst = 1.25f * g_loss * (1.0f / (float)(M_TOTAL * DIM));
}

extern "C" void kernel_launch(void* const* d_in, const int* in_sizes, int n_in,
                              void* d_out, int out_size) {
    const float* inp = (const float*)d_in[0];
    const float* cm  = (const float*)d_in[1];
    // Disambiguate by element counts (2097152 vs 1280000)
    if (n_in >= 2 && in_sizes[0] == DIM * NCODES && in_sizes[1] == M_TOTAL * DIM) {
        inp = (const float*)d_in[1];
        cm  = (const float*)d_in[0];
    }
    float* out = (float*)d_out;

    cnorm_kernel<<<(NPAD + 255) / 256, 256>>>(cm);
    vq_main_kernel<<<M_TOTAL / MTILE, 256>>>(inp, cm, out);
    if (out_size > M_TOTAL * DIM) {
        finalize_kernel<<<1, 1>>>(out + M_TOTAL * DIM);
    }
}

// round 7
// speedup vs baseline: 1.3464x; 1.3464x over previous
#include <cuda_runtime.h>
#include <cstdint>
#include <math_constants.h>

// ---------------- problem constants ----------------
#define M_TOTAL 16384
#define DIM     128
#define NCODES  10000
#define NPAD2   10240                 // 40 tiles x 256
#define NTILES  40
#define CHUNKS  12                    // per N-tile (each 4 k8-steps of K'=384)
#define NCHUNKS (NTILES * CHUNKS)     // 480
#define CHUNK_FLOATS 8192             // 256 N x 32 K' = 32 KB
#define MTILE   128

// smem: A fragments 131072 B, then 3 B-stages x 32768 B
#define A_BYTES  131072
#define B_BYTES  32768
#define SMEM_TOTAL (A_BYTES + 3 * B_BYTES)   // 229376

// ---------------- device scratch ----------------
__device__ float4 g_cnorm4[NPAD2 / 4];                 // ||c||^2 (+INF pad), 16B aligned
__device__ float  g_loss;
__device__ float  g_ctr[(size_t)NPAD2 * DIM];          // exact fp32 codebook, [n][k]
__device__ float  g_Bf[(size_t)NCHUNKS * CHUNK_FLOATS];// packed tf32 B-fragment stream

// ---------------- helpers ----------------
__device__ __forceinline__ float tf32r(float x) {
    uint32_t u;
    asm("cvt.rna.tf32.f32 %0, %1;" : "=r"(u) : "f"(x));
    return __uint_as_float(u);
}
__device__ __forceinline__ uint32_t smem_u32(const void* p) {
    uint32_t a;
    asm("{ .reg .u64 t; cvta.to.shared.u64 t, %1; cvt.u32.u64 %0, t; }"
        : "=r"(a) : "l"(p));
    return a;
}
__device__ __forceinline__ void cpa16(uint32_t dst, const void* src) {
    asm volatile("cp.async.cg.shared.global [%0], [%1], 16;" :: "r"(dst), "l"(src));
}
__device__ __forceinline__ void cpa_commit() {
    asm volatile("cp.async.commit_group;" ::: "memory");
}
__device__ __forceinline__ void mma_tf32(float* c, const float4& a, const float2& b) {
    asm volatile(
        "mma.sync.aligned.m16n8k8.row.col.f32.tf32.tf32.f32 "
        "{%0,%1,%2,%3}, {%4,%5,%6,%7}, {%8,%9}, {%0,%1,%2,%3};"
        : "+f"(c[0]), "+f"(c[1]), "+f"(c[2]), "+f"(c[3])
        : "r"(__float_as_uint(a.x)), "r"(__float_as_uint(a.y)),
          "r"(__float_as_uint(a.z)), "r"(__float_as_uint(a.w)),
          "r"(__float_as_uint(b.x)), "r"(__float_as_uint(b.y)));
}

// ---------------- kernel 0: init norms / loss ----------------
__global__ void init_kernel() {
    int j = blockIdx.x * blockDim.x + threadIdx.x;
    if (j == 0) g_loss = 0.0f;
    if (j < NPAD2) ((float*)g_cnorm4)[j] = (j < NCODES) ? 0.0f : CUDART_INF_F;
}

// ---------------- kernel 1: transpose codebook (exact fp32) + norms ----------------
__global__ void trans_kernel(const float* __restrict__ cm) {
    __shared__ float t[32][33], ps[8][33];
    int n0 = blockIdx.x * 32, k0 = blockIdx.y * 32;
    int tx = threadIdx.x, ty = threadIdx.y;
    float acc = 0.0f;
    for (int i = ty; i < 32; i += 8) {
        int n = n0 + tx;
        float v = (n < NCODES) ? cm[(size_t)(k0 + i) * NCODES + n] : 0.0f;
        t[tx][i] = v;
        acc = fmaf(v, v, acc);
    }
    ps[ty][tx] = acc;
    __syncthreads();
    for (int i = ty; i < 32; i += 8)
        g_ctr[(size_t)(n0 + i) * DIM + k0 + tx] = t[i][tx];
    if (ty == 0) {
        float s = 0.0f;
        #pragma unroll
        for (int y = 0; y < 8; ++y) s += ps[y][tx];
        if (n0 + tx < NCODES) atomicAdd(&((float*)g_cnorm4)[n0 + tx], s);
    }
}

// ---------------- kernel 2: pack codebook into B-fragment stream ----------------
// layout: ((((tile*12+c)*4+ks)*32+nt)*32+lane)*2 + r
// value:  n = tile*256 + nt*8 + lane/4 ; k' = (c*4+ks)*8 + (lane&3) + 4*r
//         term = k'>>7 (0:Ch 1:Cl 2:Ch), kk = k'&127
__global__ void pack_kernel(const float* __restrict__ cm) {
    size_t id = (size_t)blockIdx.x * 256 + threadIdx.x;   // 1,966,080 float2s
    int l  = (int)(id & 31);
    int nt = (int)((id >> 5) & 31);
    size_t rest = id >> 10;
    int ks = (int)(rest & 3);  rest >>= 2;
    int c  = (int)(rest % 12);
    int tile = (int)(rest / 12);
    int n  = tile * 256 + nt * 8 + (l >> 2);
    int sg = c * 4 + ks;                  // global kstep 0..47
    int term = sg >> 4;
    int kk0 = (sg & 15) * 8 + (l & 3);
    float2 o;
    if (n >= NCODES) { o.x = 0.0f; o.y = 0.0f; }
    else {
        float v0 = cm[(size_t)kk0 * NCODES + n];
        float v1 = cm[(size_t)(kk0 + 4) * NCODES + n];
        float h0 = tf32r(v0), h1 = tf32r(v1);
        o.x = (term == 1) ? tf32r(v0 - h0) : h0;
        o.y = (term == 1) ? tf32r(v1 - h1) : h1;
    }
    *(float2*)(g_Bf + id * 2) = o;
}

// ---------------- kernel 3: HMMA tf32 GEMM + fused argmin/gather/loss ----------
__global__ void __launch_bounds__(256, 1)
vq_main_kernel(const float* __restrict__ inp, float* __restrict__ out) {
    extern __shared__ __align__(16) char smem[];
    float* As  = (float*)smem;                 // fragment-layout A
    float* Bst = (float*)(smem + A_BYTES);     // 3 stages
    // aliases over B region (used only after mainloop)
    float* fbd  = (float*)(smem + A_BYTES);
    int*   fbi  = (int*)  (smem + A_BYTES + 2048);
    int*   sbi  = (int*)  (smem + A_BYTES + 4096);
    float* wsum = (float*)(smem + A_BYTES + 4608);
    const float* cn = (const float*)g_cnorm4;

    const int tid = threadIdx.x;
    const int w   = tid >> 5;
    const int l   = tid & 31;
    const int mw  = w >> 2;          // M-warp row (0..1), 64 samples each
    const int wn  = w & 3;           // N-warp col (0..3), 64 codes each
    const int s0  = blockIdx.x * MTILE;

    // ---- stage A fragments: unit u = mw*128 + mt*32 + ks  (ks<16: Xh, >=16: Xl) ----
    #pragma unroll
    for (int it = 0; it < 32; ++it) {
        int u  = it * 8 + w;
        int mwu = u >> 7, mt = (u >> 5) & 3, ks = u & 31;
        int kk = (ks & 15) * 8 + (l & 3);
        int m  = mwu * 64 + mt * 16 + (l >> 2);
        const float* base = inp + (size_t)(s0 + m) * DIM + kk;
        float v0 = base[0], v1 = base[8 * DIM], v2 = base[4], v3 = base[8 * DIM + 4];
        float4 o;
        if (ks < 16) {
            o.x = tf32r(v0); o.y = tf32r(v1); o.z = tf32r(v2); o.w = tf32r(v3);
        } else {
            o.x = tf32r(v0 - tf32r(v0)); o.y = tf32r(v1 - tf32r(v1));
            o.z = tf32r(v2 - tf32r(v2)); o.w = tf32r(v3 - tf32r(v3));
        }
        *(float4*)(As + (size_t)u * 128 + l * 4) = o;
    }
    __syncthreads();

    // ---- cp.async pipeline prologue: chunks 0,1,2 ----
    const uint32_t bB = smem_u32(Bst);
    #pragma unroll
    for (int g = 0; g < 3; ++g) {
        #pragma unroll
        for (int i = 0; i < 8; ++i) {
            int idx = i * 256 + tid;
            cpa16(bB + g * B_BYTES + idx * 16, g_Bf + (size_t)g * CHUNK_FLOATS + idx * 4);
        }
        cpa_commit();
    }

    float acc[4][8][4];
    #pragma unroll
    for (int mt = 0; mt < 4; ++mt)
        #pragma unroll
        for (int j = 0; j < 8; ++j)
            #pragma unroll
            for (int r = 0; r < 4; ++r) acc[mt][j][r] = 0.0f;

    float bd[8]; int bi[8];
    #pragma unroll
    for (int s = 0; s < 8; ++s) { bd[s] = CUDART_INF_F; bi[s] = 0; }

    int st = 0, sp = 0, tile = 0;
    #pragma unroll 1
    for (int g = 0; g < NCHUNKS; ++g) {
        asm volatile("cp.async.wait_group 2;" ::: "memory");
        __syncthreads();
        const float* Bs = Bst + st * CHUNK_FLOATS;

        #pragma unroll
        for (int ks = 0; ks < 4; ++ks) {
            int sg  = sp * 4 + ks;                    // 0..47
            int ksA = (sg < 16) ? sg : sg - 16;       // Xh for terms 0,1; Xl for 2
            float4 a[4];
            #pragma unroll
            for (int mt = 0; mt < 4; ++mt)
                a[mt] = *(const float4*)(As + (size_t)(mw * 128 + mt * 32 + ksA) * 128 + l * 4);
            float2 b[8];
            #pragma unroll
            for (int j = 0; j < 8; ++j)
                b[j] = *(const float2*)(Bs + ((ks * 32 + wn * 8 + j) * 32 + l) * 2);
            #pragma unroll
            for (int mt = 0; mt < 4; ++mt)
                #pragma unroll
                for (int j = 0; j < 8; ++j)
                    mma_tf32(acc[mt][j], a[mt], b[j]);
        }
        __syncthreads();

        // refill this stage for chunk g+3 (all consumers are past the barrier)
        if (g + 3 < NCHUNKS) {
            #pragma unroll
            for (int i = 0; i < 8; ++i) {
                int idx = i * 256 + tid;
                cpa16(bB + st * B_BYTES + idx * 16,
                      g_Bf + (size_t)(g + 3) * CHUNK_FLOATS + idx * 4);
            }
        }
        cpa_commit();

        // ---- tile epilogue every 12 chunks: dist = ||c||^2 - 2*dot -> argmin ----
        if (sp == CHUNKS - 1) {
            int tb = tile * 256;
            #pragma unroll
            for (int j = 0; j < 8; ++j) {
                int n0 = tb + (wn * 8 + j) * 8 + 2 * (l & 3);
                float2 c2 = *(const float2*)(cn + n0);
                #pragma unroll
                for (int mt = 0; mt < 4; ++mt) {
                    float d0 = fmaf(-2.0f, acc[mt][j][0], c2.x);
                    float d1 = fmaf(-2.0f, acc[mt][j][1], c2.y);
                    float d2 = fmaf(-2.0f, acc[mt][j][2], c2.x);
                    float d3 = fmaf(-2.0f, acc[mt][j][3], c2.y);
                    int slo = mt * 2, shi = mt * 2 + 1;
                    if (d0 < bd[slo]) { bd[slo] = d0; bi[slo] = n0; }
                    if (d1 < bd[slo]) { bd[slo] = d1; bi[slo] = n0 + 1; }
                    if (d2 < bd[shi]) { bd[shi] = d2; bi[shi] = n0; }
                    if (d3 < bd[shi]) { bd[shi] = d3; bi[shi] = n0 + 1; }
                    acc[mt][j][0] = 0.0f; acc[mt][j][1] = 0.0f;
                    acc[mt][j][2] = 0.0f; acc[mt][j][3] = 0.0f;
                }
            }
            ++tile;
            sp = 0;
        } else {
            ++sp;
        }
        st = (st == 2) ? 0 : st + 1;
    }

    // ---- reduce argmin: lanes (xor 1,2 share same rows), then across N-warps ----
    #pragma unroll
    for (int s = 0; s < 8; ++s) {
        #pragma unroll
        for (int o = 1; o < 4; o <<= 1) {
            float od = __shfl_xor_sync(0xffffffffu, bd[s], o);
            int   oi = __shfl_xor_sync(0xffffffffu, bi[s], o);
            if (od < bd[s] || (od == bd[s] && oi < bi[s])) { bd[s] = od; bi[s] = oi; }
        }
    }
    asm volatile("cp.async.wait_group 0;" ::: "memory");
    __syncthreads();                      // B region now reusable as fb arrays
    if ((l & 3) == 0) {
        #pragma unroll
        for (int s = 0; s < 8; ++s) {
            int mt = s >> 1, hi = s & 1;
            int m = mw * 64 + mt * 16 + hi * 8 + (l >> 2);
            fbd[wn * 128 + m] = bd[s];
            fbi[wn * 128 + m] = bi[s];
        }
    }
    __syncthreads();
    if (tid < 128) {
        float best = fbd[tid]; int bidx = fbi[tid];
        #pragma unroll
        for (int q = 1; q < 4; ++q) {
            float d = fbd[q * 128 + tid]; int i2 = fbi[q * 128 + tid];
            if (d < best || (d == best && i2 < bidx)) { best = d; bidx = i2; }
        }
        sbi[tid] = bidx;
    }
    __syncthreads();

    // ---- gather exact codes, write outputs, loss partial ----
    float lsum = 0.0f;
    #pragma unroll 4
    for (int rr = 0; rr < 64; ++rr) {
        int idx = rr * 256 + tid;
        int s = idx >> 7, k = idx & (DIM - 1);
        int c = sbi[s];
        float q = g_ctr[(size_t)c * DIM + k];
        float x = inp[(size_t)(s0 + s) * DIM + k];
        float d = q - x;
        out[(size_t)(s0 + s) * DIM + k] = x + d;
        lsum = fmaf(d, d, lsum);
    }
    #pragma unroll
    for (int o = 16; o > 0; o >>= 1) lsum += __shfl_xor_sync(0xffffffffu, lsum, o);
    if (l == 0) wsum[w] = lsum;
    __syncthreads();
    if (tid == 0) {
        float s = 0.0f;
        #pragma unroll
        for (int i = 0; i < 8; ++i) s += wsum[i];
        atomicAdd(&g_loss, s);
    }
}

// ---------------- kernel 4: loss = 1.25 * mean((q-x)^2) ----------------
__global__ void finalize_kernel(float* __restrict__ dst) {
    *dst = 1.25f * g_loss * (1.0f / (float)(M_TOTAL * DIM));
}

extern "C" void kernel_launch(void* const* d_in, const int* in_sizes, int n_in,
                              void* d_out, int out_size) {
    const float* inp = (const float*)d_in[0];
    const float* cm  = (const float*)d_in[1];
    if (n_in >= 2 && in_sizes[0] == DIM * NCODES && in_sizes[1] == M_TOTAL * DIM) {
        inp = (const float*)d_in[1];
        cm  = (const float*)d_in[0];
    }
    float* out = (float*)d_out;

    cudaFuncSetAttribute(vq_main_kernel,
                         cudaFuncAttributeMaxDynamicSharedMemorySize, SMEM_TOTAL);

    init_kernel<<<(NPAD2 + 255) / 256, 256>>>();
    trans_kernel<<<dim3(NPAD2 / 32, DIM / 32), dim3(32, 8)>>>(cm);
    pack_kernel<<<(int)(((size_t)NCHUNKS * CHUNK_FLOATS / 2) / 256), 256>>>(cm);
    vq_main_kernel<<<M_TOTAL / MTILE, 256, SMEM_TOTAL>>>(inp, out);
    if (out_size > M_TOTAL * DIM) {
        finalize_kernel<<<1, 1>>>(out + M_TOTAL * DIM);
    }
}

// round 8
// speedup vs baseline: 2.4688x; 1.8337x over previous
#include <cuda_runtime.h>
#include <cuda_fp16.h>
#include <cstdint>
#include <math_constants.h>

// ---------------- problem constants ----------------
#define M_TOTAL 16384
#define DIM     128
#define NCODES  10000
#define NPAD2   10240                 // 80 tiles x 128
#define NTILES2 80
#define NCHUNKS (NTILES2 * 3)         // 240 (3 chunks of 8 k16-steps per tile)
#define CHUNK_U32 8192                // 128 N x 8 steps x ... = 32 KB
#define MTILE   128

// smem: A fragments (Xh|Xl' planes) 65536 B, then 4 B-stages x 32768 B
#define A_BYTES  65536
#define B_BYTES  32768
#define SMEM_TOTAL (A_BYTES + 4 * B_BYTES)   // 196608

// ---------------- device scratch ----------------
__device__ float    g_cnorm[NPAD2];                       // ||c||^2 (+INF pad)
__device__ float    g_loss;
__device__ float    g_ctr[(size_t)NPAD2 * DIM];           // exact fp32 codebook [n][k]
__device__ uint32_t g_Bu[(size_t)NCHUNKS * CHUNK_U32];    // packed fp16 B-frag stream

// ---------------- helpers ----------------
__device__ __forceinline__ uint32_t smem_u32(const void* p) {
    uint32_t a;
    asm("{ .reg .u64 t; cvta.to.shared.u64 t, %1; cvt.u32.u64 %0, t; }"
        : "=r"(a) : "l"(p));
    return a;
}
__device__ __forceinline__ void cpa16(uint32_t dst, const void* src) {
    asm volatile("cp.async.cg.shared.global [%0], [%1], 16;" :: "r"(dst), "l"(src));
}
__device__ __forceinline__ void cpa_commit() {
    asm volatile("cp.async.commit_group;" ::: "memory");
}
__device__ __forceinline__ uint32_t h2pair(float a, float b) {
    __half2 h = __floats2half2_rn(a, b);
    return *(uint32_t*)&h;
}
__device__ __forceinline__ uint32_t l2pair(float a, float b) {
    float ah = __half2float(__float2half_rn(a));
    float bh = __half2float(__float2half_rn(b));
    return h2pair((a - ah) * 2048.0f, (b - bh) * 2048.0f);
}
__device__ __forceinline__ void mma_f16(float* c, const uint4& a,
                                        uint32_t b0, uint32_t b1) {
    asm volatile(
        "mma.sync.aligned.m16n8k16.row.col.f32.f16.f16.f32 "
        "{%0,%1,%2,%3}, {%4,%5,%6,%7}, {%8,%9}, {%0,%1,%2,%3};"
        : "+f"(c[0]), "+f"(c[1]), "+f"(c[2]), "+f"(c[3])
        : "r"(a.x), "r"(a.y), "r"(a.z), "r"(a.w), "r"(b0), "r"(b1));
}

// one 8-step chunk of MMAs: warp tile 64M x 32N, A plane selected by caller
__device__ __forceinline__ void do_chunk(float (&acc)[4][4][4], const char* As,
                                         const char* Bs, int plane, int mw,
                                         int wn, int l) {
    #pragma unroll
    for (int s = 0; s < 8; ++s) {
        uint4 a[4];
        #pragma unroll
        for (int mt = 0; mt < 4; ++mt)
            a[mt] = *(const uint4*)(As +
                ((size_t)((plane * 64 + s * 8 + mw * 4 + mt) * 32 + l)) * 16);
        uint4 b0 = *(const uint4*)(Bs + ((size_t)((s * 8 + wn * 2 + 0) * 32 + l)) * 16);
        uint4 b1 = *(const uint4*)(Bs + ((size_t)((s * 8 + wn * 2 + 1) * 32 + l)) * 16);
        #pragma unroll
        for (int mt = 0; mt < 4; ++mt) {
            mma_f16(acc[mt][0], a[mt], b0.x, b0.y);
            mma_f16(acc[mt][1], a[mt], b0.z, b0.w);
            mma_f16(acc[mt][2], a[mt], b1.x, b1.y);
            mma_f16(acc[mt][3], a[mt], b1.z, b1.w);
        }
    }
}

// ---------------- kernel 0: init norms / loss ----------------
__global__ void init_kernel() {
    int j = blockIdx.x * blockDim.x + threadIdx.x;
    if (j == 0) g_loss = 0.0f;
    if (j < NPAD2) g_cnorm[j] = (j < NCODES) ? 0.0f : CUDART_INF_F;
}

// ---------------- kernel 1: transpose codebook (exact fp32) + norms ------------
__global__ void trans_kernel(const float* __restrict__ cm) {
    __shared__ float t[32][33], ps[8][33];
    int n0 = blockIdx.x * 32, k0 = blockIdx.y * 32;
    int tx = threadIdx.x, ty = threadIdx.y;
    float acc = 0.0f;
    for (int i = ty; i < 32; i += 8) {
        int n = n0 + tx;
        float v = (n < NCODES) ? cm[(size_t)(k0 + i) * NCODES + n] : 0.0f;
        t[tx][i] = v;
        acc = fmaf(v, v, acc);
    }
    ps[ty][tx] = acc;
    __syncthreads();
    for (int i = ty; i < 32; i += 8)
        g_ctr[(size_t)(n0 + i) * DIM + k0 + tx] = t[i][tx];
    if (ty == 0) {
        float s = 0.0f;
        #pragma unroll
        for (int y = 0; y < 8; ++y) s += ps[y][tx];
        if (n0 + tx < NCODES) atomicAdd(&g_cnorm[n0 + tx], s);
    }
}

// ---------------- kernel 2: pack codebook into fp16 B-fragment stream ----------
// uint32 id bits: r2(2) | l(5) | ngp(3) | s(3) | cg(rest); cg = tile*3 + c
// chunk c: 0,1 -> Ch ; 2 -> Cl' (=fp16((v-fp16(v))*2048))
__global__ void pack_kernel(const float* __restrict__ cm) {
    size_t id = (size_t)blockIdx.x * 256 + threadIdx.x;   // 1,966,080
    int r2 = (int)(id & 3);
    int l  = (int)((id >> 2) & 31);
    int ngp= (int)((id >> 7) & 7);
    int s  = (int)((id >> 10) & 7);
    int cg = (int)(id >> 13);
    int tile = cg / 3, c = cg % 3;
    int ng = ngp * 2 + (r2 >> 1);
    int r  = r2 & 1;
    int n  = tile * 128 + ng * 8 + (l >> 2);
    int k  = s * 16 + r * 8 + 2 * (l & 3);
    uint32_t o = 0u;
    if (n < NCODES) {
        float v0 = cm[(size_t)k * NCODES + n];
        float v1 = cm[(size_t)(k + 1) * NCODES + n];
        o = (c == 2) ? l2pair(v0, v1) : h2pair(v0, v1);
    }
    g_Bu[id] = o;
}

// ---------------- kernel 3: fp16-split HMMA GEMM + fused argmin/gather/loss ----
__global__ void __launch_bounds__(256, 1)
vq_main_kernel(const float* __restrict__ inp, float* __restrict__ out) {
    extern __shared__ __align__(16) char smem[];
    char* As  = smem;
    char* Bst = smem + A_BYTES;
    float* fbd  = (float*)(smem + A_BYTES);
    int*   fbi  = (int*)  (smem + A_BYTES + 2048);
    int*   sbi  = (int*)  (smem + A_BYTES + 4096);
    float* wsum = (float*)(smem + A_BYTES + 4608);
    const float* cn = g_cnorm;

    const int tid = threadIdx.x;
    const int w   = tid >> 5;
    const int l   = tid & 31;
    const int mw  = w >> 2;          // 0..1: 64-sample half
    const int wn  = w & 3;           // 0..3: 32-code slice
    const int s0  = blockIdx.x * MTILE;

    // ---- stage A: fp16 fragments, plane0 = Xh, plane1 = Xl' (= (x-xh)*2048) ----
    #pragma unroll
    for (int it = 0; it < 8; ++it) {
        int u = it * 8 + w;                 // 0..63: s*8 + mtile
        int s = u >> 3, mtg = u & 7;
        int m0 = mtg * 16 + (l >> 2);
        int kb = s * 16 + 2 * (l & 3);
        const float* p0 = inp + (size_t)(s0 + m0) * DIM + kb;
        float2 v00 = *(const float2*)(p0);
        float2 v10 = *(const float2*)(p0 + 8 * DIM);
        float2 v01 = *(const float2*)(p0 + 8);
        float2 v11 = *(const float2*)(p0 + 8 * DIM + 8);
        uint4 h, lo;
        h.x  = h2pair(v00.x, v00.y);  h.y  = h2pair(v10.x, v10.y);
        h.z  = h2pair(v01.x, v01.y);  h.w  = h2pair(v11.x, v11.y);
        lo.x = l2pair(v00.x, v00.y);  lo.y = l2pair(v10.x, v10.y);
        lo.z = l2pair(v01.x, v01.y);  lo.w = l2pair(v11.x, v11.y);
        *(uint4*)(As + ((size_t)((      u) * 32 + l)) * 16) = h;
        *(uint4*)(As + ((size_t)((64 +  u) * 32 + l)) * 16) = lo;
    }
    __syncthreads();

    // ---- cp.async prologue: chunks 0..2 into stages 0..2 (of 4) ----
    const uint32_t bB = smem_u32(Bst);
    #pragma unroll
    for (int g = 0; g < 3; ++g) {
        #pragma unroll
        for (int i = 0; i < 8; ++i) {
            int idx = i * 256 + tid;
            cpa16(bB + g * B_BYTES + idx * 16,
                  g_Bu + (size_t)g * CHUNK_U32 + (size_t)idx * 4);
        }
        cpa_commit();
    }

    float accM[4][4][4], accC[4][4][4];
    #pragma unroll
    for (int mt = 0; mt < 4; ++mt)
        #pragma unroll
        for (int j = 0; j < 4; ++j)
            #pragma unroll
            for (int r = 0; r < 4; ++r) { accM[mt][j][r] = 0.0f; accC[mt][j][r] = 0.0f; }

    float bd[8]; int bi[8];
    #pragma unroll
    for (int s = 0; s < 8; ++s) { bd[s] = CUDART_INF_F; bi[s] = 0; }

    int sp = 0, tile = 0;
    #pragma unroll 1
    for (int g = 0; g < NCHUNKS; ++g) {
        asm volatile("cp.async.wait_group 2;" ::: "memory");
        __syncthreads();                       // single barrier per chunk

        // refill stage (g+3)&3 for chunk g+3 (distinct from stages g..g+2)
        if (g + 3 < NCHUNKS) {
            #pragma unroll
            for (int i = 0; i < 8; ++i) {
                int idx = i * 256 + tid;
                cpa16(bB + ((g + 3) & 3) * B_BYTES + idx * 16,
                      g_Bu + (size_t)(g + 3) * CHUNK_U32 + (size_t)idx * 4);
            }
        }
        cpa_commit();

        const char* Bs = Bst + (size_t)(g & 3) * B_BYTES;
        if (sp == 0)      do_chunk(accM, As, Bs, 0, mw, wn, l);  // Xh * Ch
        else if (sp == 1) do_chunk(accC, As, Bs, 1, mw, wn, l);  // Xl' * Ch
        else              do_chunk(accC, As, Bs, 0, mw, wn, l);  // Xh * Cl'

        if (sp == 2) {
            // dist = ||c||^2 - 2*(main + cross/2048) ; fold into running argmin
            int tb = tile * 128;
            #pragma unroll
            for (int j = 0; j < 4; ++j) {
                int n0 = tb + wn * 32 + j * 8 + 2 * (l & 3);
                float2 c2 = *(const float2*)(cn + n0);
                #pragma unroll
                for (int mt = 0; mt < 4; ++mt) {
                    float d0 = fmaf(-2.0f, accM[mt][j][0],
                               fmaf(-0.0009765625f, accC[mt][j][0], c2.x));
                    float d1 = fmaf(-2.0f, accM[mt][j][1],
                               fmaf(-0.0009765625f, accC[mt][j][1], c2.y));
                    float d2 = fmaf(-2.0f, accM[mt][j][2],
                               fmaf(-0.0009765625f, accC[mt][j][2], c2.x));
                    float d3 = fmaf(-2.0f, accM[mt][j][3],
                               fmaf(-0.0009765625f, accC[mt][j][3], c2.y));
                    int slo = mt * 2, shi = mt * 2 + 1;
                    if (d0 < bd[slo]) { bd[slo] = d0; bi[slo] = n0; }
                    if (d1 < bd[slo]) { bd[slo] = d1; bi[slo] = n0 + 1; }
                    if (d2 < bd[shi]) { bd[shi] = d2; bi[shi] = n0; }
                    if (d3 < bd[shi]) { bd[shi] = d3; bi[shi] = n0 + 1; }
                    #pragma unroll
                    for (int r = 0; r < 4; ++r) { accM[mt][j][r] = 0.0f; accC[mt][j][r] = 0.0f; }
                }
            }
            ++tile;
            sp = 0;
        } else {
            ++sp;
        }
    }

    // ---- reduce argmin across lanes sharing the same row (xor 1,2) ----
    #pragma unroll
    for (int s = 0; s < 8; ++s) {
        #pragma unroll
        for (int o = 1; o < 4; o <<= 1) {
            float od = __shfl_xor_sync(0xffffffffu, bd[s], o);
            int   oi = __shfl_xor_sync(0xffffffffu, bi[s], o);
            if (od < bd[s] || (od == bd[s] && oi < bi[s])) { bd[s] = od; bi[s] = oi; }
        }
    }
    asm volatile("cp.async.wait_group 0;" ::: "memory");
    __syncthreads();                  // B region reusable
    if ((l & 3) == 0) {
        #pragma unroll
        for (int s = 0; s < 8; ++s) {
            int mt = s >> 1, half = s & 1;
            int m = mw * 64 + mt * 16 + half * 8 + (l >> 2);
            fbd[wn * 128 + m] = bd[s];
            fbi[wn * 128 + m] = bi[s];
        }
    }
    __syncthreads();
    if (tid < 128) {
        float best = fbd[tid]; int bidx = fbi[tid];
        #pragma unroll
        for (int q = 1; q < 4; ++q) {
            float d = fbd[q * 128 + tid]; int i2 = fbi[q * 128 + tid];
            if (d < best || (d == best && i2 < bidx)) { best = d; bidx = i2; }
        }
        sbi[tid] = bidx;
    }
    __syncthreads();

    // ---- gather exact fp32 codes, write outputs, loss partial ----
    float lsum = 0.0f;
    #pragma unroll 4
    for (int rr = 0; rr < 64; ++rr) {
        int idx = rr * 256 + tid;
        int s = idx >> 7, k = idx & (DIM - 1);
        int c = sbi[s];
        float q = g_ctr[(size_t)c * DIM + k];
        float x = inp[(size_t)(s0 + s) * DIM + k];
        float d = q - x;
        out[(size_t)(s0 + s) * DIM + k] = x + d;
        lsum = fmaf(d, d, lsum);
    }
    #pragma unroll
    for (int o = 16; o > 0; o >>= 1) lsum += __shfl_xor_sync(0xffffffffu, lsum, o);
    if (l == 0) wsum[w] = lsum;
    __syncthreads();
    if (tid == 0) {
        float s = 0.0f;
        #pragma unroll
        for (int i = 0; i < 8; ++i) s += wsum[i];
        atomicAdd(&g_loss, s);
    }
}

// ---------------- kernel 4: loss = 1.25 * mean((q-x)^2) ----------------
__global__ void finalize_kernel(float* __restrict__ dst) {
    *dst = 1.25f * g_loss * (1.0f / (float)(M_TOTAL * DIM));
}

extern "C" void kernel_launch(void* const* d_in, const int* in_sizes, int n_in,
                              void* d_out, int out_size) {
    const float* inp = (const float*)d_in[0];
    const float* cm  = (const float*)d_in[1];
    if (n_in >= 2 && in_sizes[0] == DIM * NCODES && in_sizes[1] == M_TOTAL * DIM) {
        inp = (const float*)d_in[1];
        cm  = (const float*)d_in[0];
    }
    float* out = (float*)d_out;

    cudaFuncSetAttribute(vq_main_kernel,
                         cudaFuncAttributeMaxDynamicSharedMemorySize, SMEM_TOTAL);

    init_kernel<<<(NPAD2 + 255) / 256, 256>>>();
    trans_kernel<<<dim3(NPAD2 / 32, DIM / 32), dim3(32, 8)>>>(cm);
    pack_kernel<<<(int)(((size_t)NCHUNKS * CHUNK_U32) / 256), 256>>>(cm);
    vq_main_kernel<<<M_TOTAL / MTILE, 256, SMEM_TOTAL>>>(inp, out);
    if (out_size > M_TOTAL * DIM) {
        finalize_kernel<<<1, 1>>>(out + M_TOTAL * DIM);
    }
}

// round 9
// speedup vs baseline: 2.6337x; 1.0668x over previous
#include <cuda_runtime.h>
#include <cuda_fp16.h>
#include <cstdint>
#include <math_constants.h>

// ---------------- problem constants ----------------
#define M_TOTAL 16384
#define DIM     128
#define NCODES  10000
#define NPAD2   10240                 // 80 tiles x 128
#define NTILES2 80
#define NCHUNKS (NTILES2 * 3)         // 240 (3 chunks of 8 k16-steps per tile)
#define CHUNK_U32 8192                // 128 N x 8 steps = 32 KB, as 4 x 8KB wn-slices
#define SLICE_U32 2048                // per-wn slice: 8 KB
#define MTILE   128

// smem: A fragments (Xh|Xl' planes) 65536 B, then 4 B-stages x 32768 B
#define A_BYTES  65536
#define B_BYTES  32768
#define SMEM_TOTAL (A_BYTES + 4 * B_BYTES)   // 196608

// ---------------- device scratch ----------------
__device__ float    g_cnorm[NPAD2];                       // ||c||^2 (+INF pad)
__device__ float    g_loss;
__device__ float    g_ctr[(size_t)NPAD2 * DIM];           // exact fp32 codebook [n][k]
__device__ uint32_t g_Bu[(size_t)NCHUNKS * CHUNK_U32];    // packed fp16 B-frag stream

// ---------------- helpers ----------------
__device__ __forceinline__ uint32_t smem_u32(const void* p) {
    uint32_t a;
    asm("{ .reg .u64 t; cvta.to.shared.u64 t, %1; cvt.u32.u64 %0, t; }"
        : "=r"(a) : "l"(p));
    return a;
}
__device__ __forceinline__ void cpa16(uint32_t dst, const void* src) {
    asm volatile("cp.async.cg.shared.global [%0], [%1], 16;" :: "r"(dst), "l"(src));
}
__device__ __forceinline__ void cpa_commit() {
    asm volatile("cp.async.commit_group;" ::: "memory");
}
__device__ __forceinline__ void pair_bar(int wn) {
    asm volatile("bar.sync %0, 64;" :: "r"(wn + 1) : "memory");
}
__device__ __forceinline__ uint32_t h2pair(float a, float b) {
    __half2 h = __floats2half2_rn(a, b);
    return *(uint32_t*)&h;
}
__device__ __forceinline__ uint32_t l2pair(float a, float b) {
    float ah = __half2float(__float2half_rn(a));
    float bh = __half2float(__float2half_rn(b));
    return h2pair((a - ah) * 2048.0f, (b - bh) * 2048.0f);
}
__device__ __forceinline__ void mma_f16(float* c, const uint4& a,
                                        uint32_t b0, uint32_t b1) {
    asm volatile(
        "mma.sync.aligned.m16n8k16.row.col.f32.f16.f16.f32 "
        "{%0,%1,%2,%3}, {%4,%5,%6,%7}, {%8,%9}, {%0,%1,%2,%3};"
        : "+f"(c[0]), "+f"(c[1]), "+f"(c[2]), "+f"(c[3])
        : "r"(a.x), "r"(a.y), "r"(a.z), "r"(a.w), "r"(b0), "r"(b1));
}

// one 8-step chunk of MMAs: warp tile 64M x 32N; Bsl = this pair's 8KB slice
__device__ __forceinline__ void do_chunk(float (&acc)[4][4][4], const char* As,
                                         const char* Bsl, int plane, int mw, int l) {
    #pragma unroll
    for (int s = 0; s < 8; ++s) {
        uint4 a[4];
        #pragma unroll
        for (int mt = 0; mt < 4; ++mt)
            a[mt] = *(const uint4*)(As +
                ((size_t)((plane * 64 + s * 8 + mw * 4 + mt) * 32 + l)) * 16);
        uint4 b0 = *(const uint4*)(Bsl + ((size_t)((s * 2 + 0) * 32 + l)) * 16);
        uint4 b1 = *(const uint4*)(Bsl + ((size_t)((s * 2 + 1) * 32 + l)) * 16);
        #pragma unroll
        for (int mt = 0; mt < 4; ++mt) {
            mma_f16(acc[mt][0], a[mt], b0.x, b0.y);
            mma_f16(acc[mt][1], a[mt], b0.z, b0.w);
            mma_f16(acc[mt][2], a[mt], b1.x, b1.y);
            mma_f16(acc[mt][3], a[mt], b1.z, b1.w);
        }
    }
}

// ---------------- kernel 0: init norms / loss ----------------
__global__ void init_kernel() {
    int j = blockIdx.x * blockDim.x + threadIdx.x;
    if (j == 0) g_loss = 0.0f;
    if (j < NPAD2) g_cnorm[j] = (j < NCODES) ? 0.0f : CUDART_INF_F;
}

// ---------------- kernel 1: transpose codebook (exact fp32) + norms ------------
__global__ void trans_kernel(const float* __restrict__ cm) {
    __shared__ float t[32][33], ps[8][33];
    int n0 = blockIdx.x * 32, k0 = blockIdx.y * 32;
    int tx = threadIdx.x, ty = threadIdx.y;
    float acc = 0.0f;
    for (int i = ty; i < 32; i += 8) {
        int n = n0 + tx;
        float v = (n < NCODES) ? cm[(size_t)(k0 + i) * NCODES + n] : 0.0f;
        t[tx][i] = v;
        acc = fmaf(v, v, acc);
    }
    ps[ty][tx] = acc;
    __syncthreads();
    for (int i = ty; i < 32; i += 8)
        g_ctr[(size_t)(n0 + i) * DIM + k0 + tx] = t[i][tx];
    if (ty == 0) {
        float s = 0.0f;
        #pragma unroll
        for (int y = 0; y < 8; ++y) s += ps[y][tx];
        if (n0 + tx < NCODES) atomicAdd(&g_cnorm[n0 + tx], s);
    }
}

// ---------------- kernel 2: pack codebook into fp16 B-fragment stream ----------
// u32 id bits (LSB first): r2(2) | l(5) | j2(1) | s(3) | wn(2) | cg
// chunk cg = tile*3 + c ; c: 0,1 -> Ch ; 2 -> Cl' (=fp16((v-fp16(v))*2048))
// element: n = tile*128 + (wn*4 + j2*2 + (r2>>1))*8 + (l>>2)
//          k = s*16 + (r2&1)*8 + 2*(l&3)   (pair covers k, k+1)
__global__ void pack_kernel(const float* __restrict__ cm) {
    size_t id = (size_t)blockIdx.x * 256 + threadIdx.x;   // 1,966,080
    int r2 = (int)(id & 3);
    int l  = (int)((id >> 2) & 31);
    int j2 = (int)((id >> 7) & 1);
    int s  = (int)((id >> 8) & 7);
    int wn = (int)((id >> 11) & 3);
    int cg = (int)(id >> 13);
    int tile = cg / 3, c = cg % 3;
    int n  = tile * 128 + (wn * 4 + j2 * 2 + (r2 >> 1)) * 8 + (l >> 2);
    int k  = s * 16 + (r2 & 1) * 8 + 2 * (l & 3);
    uint32_t o = 0u;
    if (n < NCODES) {
        float v0 = cm[(size_t)k * NCODES + n];
        float v1 = cm[(size_t)(k + 1) * NCODES + n];
        o = (c == 2) ? l2pair(v0, v1) : h2pair(v0, v1);
    }
    g_Bu[id] = o;
}

// ---------------- kernel 3: fp16-split HMMA GEMM, pair-private pipelines -------
__global__ void __launch_bounds__(256, 1)
vq_main_kernel(const float* __restrict__ inp, float* __restrict__ out) {
    extern __shared__ __align__(16) char smem[];
    char* As  = smem;
    char* Bst = smem + A_BYTES;
    float* fbd  = (float*)(smem + A_BYTES);
    int*   fbi  = (int*)  (smem + A_BYTES + 2048);
    int*   sbi  = (int*)  (smem + A_BYTES + 4096);
    float* wsum = (float*)(smem + A_BYTES + 4608);
    const float* cn = g_cnorm;

    const int tid = threadIdx.x;
    const int w   = tid >> 5;
    const int l   = tid & 31;
    const int mw  = w >> 2;          // 0..1: 64-sample half
    const int wn  = w & 3;           // 0..3: 32-code slice (pair id)
    const int pt  = mw * 32 + l;     // thread id within the pair (0..63)
    const int s0  = blockIdx.x * MTILE;

    // ---- stage A: fp16 fragments, plane0 = Xh, plane1 = Xl' (= (x-xh)*2048) ----
    #pragma unroll
    for (int it = 0; it < 8; ++it) {
        int u = it * 8 + w;                 // 0..63: s*8 + mtile
        int s = u >> 3, mtg = u & 7;
        int m0 = mtg * 16 + (l >> 2);
        int kb = s * 16 + 2 * (l & 3);
        const float* p0 = inp + (size_t)(s0 + m0) * DIM + kb;
        float2 v00 = *(const float2*)(p0);
        float2 v10 = *(const float2*)(p0 + 8 * DIM);
        float2 v01 = *(const float2*)(p0 + 8);
        float2 v11 = *(const float2*)(p0 + 8 * DIM + 8);
        uint4 h, lo;
        h.x  = h2pair(v00.x, v00.y);  h.y  = h2pair(v10.x, v10.y);
        h.z  = h2pair(v01.x, v01.y);  h.w  = h2pair(v11.x, v11.y);
        lo.x = l2pair(v00.x, v00.y);  lo.y = l2pair(v10.x, v10.y);
        lo.z = l2pair(v01.x, v01.y);  lo.w = l2pair(v11.x, v11.y);
        *(uint4*)(As + ((size_t)((      u) * 32 + l)) * 16) = h;
        *(uint4*)(As + ((size_t)((64 +  u) * 32 + l)) * 16) = lo;
    }
    __syncthreads();

    // ---- pair-private cp.async prologue: this pair's slices of chunks 0..2 ----
    const uint32_t bB = smem_u32(Bst) + wn * (SLICE_U32 * 4);
    #pragma unroll
    for (int g = 0; g < 3; ++g) {
        #pragma unroll
        for (int i = 0; i < 8; ++i) {
            int idx = i * 64 + pt;
            cpa16(bB + g * B_BYTES + idx * 16,
                  g_Bu + (size_t)g * CHUNK_U32 + wn * SLICE_U32 + (size_t)idx * 4);
        }
        cpa_commit();
    }

    float accM[4][4][4], accC[4][4][4];
    #pragma unroll
    for (int mt = 0; mt < 4; ++mt)
        #pragma unroll
        for (int j = 0; j < 4; ++j)
            #pragma unroll
            for (int r = 0; r < 4; ++r) { accM[mt][j][r] = 0.0f; accC[mt][j][r] = 0.0f; }

    float bd[8]; int bi[8];
    #pragma unroll
    for (int s = 0; s < 8; ++s) { bd[s] = CUDART_INF_F; bi[s] = 0; }

    int sp = 0, tile = 0;
    #pragma unroll 1
    for (int g = 0; g < NCHUNKS; ++g) {
        asm volatile("cp.async.wait_group 2;" ::: "memory");
        pair_bar(wn);                    // partner's half of this slice landed too

        // refill stage (g+3)&3 for chunk g+3 (slot of chunk g-1: pair consumed it)
        if (g + 3 < NCHUNKS) {
            #pragma unroll
            for (int i = 0; i < 8; ++i) {
                int idx = i * 64 + pt;
                cpa16(bB + ((g + 3) & 3) * B_BYTES + idx * 16,
                      g_Bu + (size_t)(g + 3) * CHUNK_U32 + wn * SLICE_U32 + (size_t)idx * 4);
            }
        }
        cpa_commit();

        const char* Bsl = Bst + (size_t)(g & 3) * B_BYTES + (size_t)wn * (SLICE_U32 * 4);
        if (sp == 0)      do_chunk(accM, As, Bsl, 0, mw, l);  // Xh * Ch
        else if (sp == 1) do_chunk(accC, As, Bsl, 1, mw, l);  // Xl' * Ch
        else              do_chunk(accC, As, Bsl, 0, mw, l);  // Xh * Cl'

        if (sp == 2) {
            // dist = ||c||^2 - 2*(main + cross/2048) ; fold into running argmin
            int tb = tile * 128;
            #pragma unroll
            for (int j = 0; j < 4; ++j) {
                int n0 = tb + wn * 32 + j * 8 + 2 * (l & 3);
                float2 c2 = *(const float2*)(cn + n0);
                #pragma unroll
                for (int mt = 0; mt < 4; ++mt) {
                    float d0 = fmaf(-2.0f, accM[mt][j][0],
                               fmaf(-0.0009765625f, accC[mt][j][0], c2.x));
                    float d1 = fmaf(-2.0f, accM[mt][j][1],
                               fmaf(-0.0009765625f, accC[mt][j][1], c2.y));
                    float d2 = fmaf(-2.0f, accM[mt][j][2],
                               fmaf(-0.0009765625f, accC[mt][j][2], c2.x));
                    float d3 = fmaf(-2.0f, accM[mt][j][3],
                               fmaf(-0.0009765625f, accC[mt][j][3], c2.y));
                    int slo = mt * 2, shi = mt * 2 + 1;
                    if (d0 < bd[slo]) { bd[slo] = d0; bi[slo] = n0; }
                    if (d1 < bd[slo]) { bd[slo] = d1; bi[slo] = n0 + 1; }
                    if (d2 < bd[shi]) { bd[shi] = d2; bi[shi] = n0; }
                    if (d3 < bd[shi]) { bd[shi] = d3; bi[shi] = n0 + 1; }
                    #pragma unroll
                    for (int r = 0; r < 4; ++r) { accM[mt][j][r] = 0.0f; accC[mt][j][r] = 0.0f; }
                }
            }
            ++tile;
            sp = 0;
        } else {
            ++sp;
        }
    }

    // ---- reduce argmin across lanes sharing the same row (xor 1,2) ----
    #pragma unroll
    for (int s = 0; s < 8; ++s) {
        #pragma unroll
        for (int o = 1; o < 4; o <<= 1) {
            float od = __shfl_xor_sync(0xffffffffu, bd[s], o);
            int   oi = __shfl_xor_sync(0xffffffffu, bi[s], o);
            if (od < bd[s] || (od == bd[s] && oi < bi[s])) { bd[s] = od; bi[s] = oi; }
        }
    }
    asm volatile("cp.async.wait_group 0;" ::: "memory");
    __syncthreads();                  // B region reusable
    if ((l & 3) == 0) {
        #pragma unroll
        for (int s = 0; s < 8; ++s) {
            int mt = s >> 1, half = s & 1;
            int m = mw * 64 + mt * 16 + half * 8 + (l >> 2);
            fbd[wn * 128 + m] = bd[s];
            fbi[wn * 128 + m] = bi[s];
        }
    }
    __syncthreads();
    if (tid < 128) {
        float best = fbd[tid]; int bidx = fbi[tid];
        #pragma unroll
        for (int q = 1; q < 4; ++q) {
            float d = fbd[q * 128 + tid]; int i2 = fbi[q * 128 + tid];
            if (d < best || (d == best && i2 < bidx)) { best = d; bidx = i2; }
        }
        sbi[tid] = bidx;
    }
    __syncthreads();

    // ---- gather exact fp32 codes, write outputs, loss partial ----
    float lsum = 0.0f;
    #pragma unroll 4
    for (int rr = 0; rr < 64; ++rr) {
        int idx = rr * 256 + tid;
        int s = idx >> 7, k = idx & (DIM - 1);
        int c = sbi[s];
        float q = g_ctr[(size_t)c * DIM + k];
        float x = inp[(size_t)(s0 + s) * DIM + k];
        float d = q - x;
        out[(size_t)(s0 + s) * DIM + k] = x + d;
        lsum = fmaf(d, d, lsum);
    }
    #pragma unroll
    for (int o = 16; o > 0; o >>= 1) lsum += __shfl_xor_sync(0xffffffffu, lsum, o);
    if (l == 0) wsum[w] = lsum;
    __syncthreads();
    if (tid == 0) {
        float s = 0.0f;
        #pragma unroll
        for (int i = 0; i < 8; ++i) s += wsum[i];
        atomicAdd(&g_loss, s);
    }
}

// ---------------- kernel 4: loss = 1.25 * mean((q-x)^2) ----------------
__global__ void finalize_kernel(float* __restrict__ dst) {
    *dst = 1.25f * g_loss * (1.0f / (float)(M_TOTAL * DIM));
}

extern "C" void kernel_launch(void* const* d_in, const int* in_sizes, int n_in,
                              void* d_out, int out_size) {
    const float* inp = (const float*)d_in[0];
    const float* cm  = (const float*)d_in[1];
    if (n_in >= 2 && in_sizes[0] == DIM * NCODES && in_sizes[1] == M_TOTAL * DIM) {
        inp = (const float*)d_in[1];
        cm  = (const float*)d_in[0];
    }
    float* out = (float*)d_out;

    cudaFuncSetAttribute(vq_main_kernel,
                         cudaFuncAttributeMaxDynamicSharedMemorySize, SMEM_TOTAL);

    init_kernel<<<(NPAD2 + 255) / 256, 256>>>();
    trans_kernel<<<dim3(NPAD2 / 32, DIM / 32), dim3(32, 8)>>>(cm);
    pack_kernel<<<(int)(((size_t)NCHUNKS * CHUNK_U32) / 256), 256>>>(cm);
    vq_main_kernel<<<M_TOTAL / MTILE, 256, SMEM_TOTAL>>>(inp, out);
    if (out_size > M_TOTAL * DIM) {
        finalize_kernel<<<1, 1>>>(out + M_TOTAL * DIM);
    }
}